// round 10
// baseline (speedup 1.0000x reference)
#include <cuda_runtime.h>
#include <stdint.h>

#define BB 64
#define TT 512
#define UU 256

__device__ float g_ll[BB];

// ---------------------------------------------------------------------------
__device__ __forceinline__ uint32_t s2u(const void* p) {
    uint32_t r;
    asm("{ .reg .u64 t; cvta.to.shared.u64 t, %1; cvt.u32.u64 %0, t; }" : "=r"(r) : "l"(p));
    return r;
}
__device__ __forceinline__ unsigned long long pack2(float lo, float hi) {
    unsigned long long r;
    asm("mov.b64 %0, {%1, %2};" : "=l"(r) : "f"(lo), "f"(hi));
    return r;
}
__device__ __forceinline__ float rcp_approx(float v) {
    float r;
    asm("rcp.approx.f32 %0, %1;" : "=f"(r) : "f"(v));
    return r;
}

struct __align__(16) Smem {
    float ea[2][UU];           // x state, double-buffered by step parity (1KB stride)
    float c0;                  // broadcast of pot[b,0,0]
    unsigned long long mb[2];  // mbarriers, count=1 (u0 arrive.expect_tx per phase)
    float red[8];
    float sscore;
};

// ---------------------------------------------------------------------------
// k_forward: one 2-CTA cluster per batch. u-split: CTA rank r computes FINAL
// x_t[u] for u in [r*128, r*128+128). Thread pair (u_loc = tid>>1, h = tid&1)
// each covers 64 local-v + 64 peer-v (E in 64 packed-f32x2 regs), shfl-combined.
// Finished x is STS'd locally AND st.async'd straight into the peer's ea
// (zero-copy receive). The mbarrier wait sits BETWEEN the two FFMA halves so
// DSMEM transit overlaps the local-half dot product. ea double-buffered.
// ---------------------------------------------------------------------------
__global__ __launch_bounds__(256, 1) __cluster_dims__(2, 1, 1)
void k_forward(const float* __restrict__ pot,     // [B,T,U]
               const int*   __restrict__ tags,    // [B,T]
               const int*   __restrict__ seqlen,  // [B]
               const float* __restrict__ trans)   // [U,U]
{
    __shared__ Smem sm;
    const int tid  = threadIdx.x;
    const int rank = blockIdx.x & 1;
    const int b    = blockIdx.x >> 1;
    const int lane = tid & 31;
    const int wid  = tid >> 5;
    const int h    = tid & 1;
    const int u    = rank * 128 + (tid >> 1);   // my output tag
    const int L    = seqlen[b];

    if (tid == 0) {
        asm volatile("mbarrier.init.shared.b64 [%0], 1;" :: "r"(s2u(&sm.mb[0])) : "memory");
        asm volatile("mbarrier.init.shared.b64 [%0], 1;" :: "r"(s2u(&sm.mb[1])) : "memory");
    }
    __syncthreads();
    asm volatile("barrier.cluster.arrive.aligned;" ::: "memory");

    // ---- E[v][u] into 64 f32x2 regs: em[0..31] local-half v, em[32..63] peer ----
    const int vloc = rank * 128 + h * 64;          // my local v-base
    const int vper = (rank ^ 1) * 128 + h * 64;    // peer v-base
    unsigned long long em[64];
    #pragma unroll
    for (int i = 0; i < 16; i++) {
        int v = vloc + 4 * i;
        em[2*i]   = pack2(__expf(__ldg(&trans[(v+0)*UU + u])), __expf(__ldg(&trans[(v+1)*UU + u])));
        em[2*i+1] = pack2(__expf(__ldg(&trans[(v+2)*UU + u])), __expf(__ldg(&trans[(v+3)*UU + u])));
    }
    #pragma unroll
    for (int i = 0; i < 16; i++) {
        int v = vper + 4 * i;
        em[32+2*i] = pack2(__expf(__ldg(&trans[(v+0)*UU + u])), __expf(__ldg(&trans[(v+1)*UU + u])));
        em[33+2*i] = pack2(__expf(__ldg(&trans[(v+2)*UU + u])), __expf(__ldg(&trans[(v+3)*UU + u])));
    }
    asm volatile("barrier.cluster.wait.aligned;" ::: "memory");

    // ---- path score (rank 0 only; CTA-uniform) ----
    if (rank == 0) {
        float sc = 0.0f;
        for (int t = tid; t < L; t += 256) {
            int tg = __ldg(&tags[b * TT + t]);
            sc += __ldg(&pot[(b * TT + t) * UU + tg]);
            if (t >= 1) {
                int tp = __ldg(&tags[b * TT + t - 1]);
                sc += __ldg(&trans[tp * UU + tg]);
            }
        }
        #pragma unroll
        for (int o = 16; o; o >>= 1) sc += __shfl_xor_sync(0xffffffffu, sc, o);
        if (lane == 0) sm.red[wid] = sc;
        __syncthreads();
        if (tid == 0)
            sm.sscore = (sm.red[0] + sm.red[1]) + (sm.red[2] + sm.red[3])
                      + (sm.red[4] + sm.red[5]) + (sm.red[6] + sm.red[7]);
    }

    // ---- prefill ea[0] with x0 = exp(pot0 - C0) for ALL 256 u (both CTAs) ----
    float p0 = pot[b * TT * UU + tid];
    if (tid == 0) sm.c0 = p0;
    __syncthreads();
    const float C0 = sm.c0;
    sm.ea[0][tid] = __expf(p0 - C0);   // x0[0] == 1
    float Lq = C0;

    // ---- prime mb[0] phase 0: t=1's wait passes instantly ----
    if (tid == 0)
        asm volatile("mbarrier.arrive.expect_tx.shared.b64 _, [%0], 0;"
                     :: "r"(s2u(&sm.mb[0])) : "memory");

    // ---- pot pipeline (2-deep), indexed by my u ----
    float pe   = __expf(__ldg(&pot[(b * TT + 1) * UU + u]));   // pe for t=1
    float potR = __ldg(&pot[(b * TT + 2) * UU + u]);           // raw for t=2

    // hoisted addresses
    const uint32_t l_ea   = s2u(&sm.ea[0][0]);
    const uint32_t l_mb   = s2u(&sm.mb[0]);
    const uint32_t a_loc  = l_ea + (uint32_t)vloc * 4u;   // + pb*1024 per iter
    const uint32_t a_per  = l_ea + (uint32_t)vper * 4u;
    const uint32_t l_eau  = l_ea + (uint32_t)u * 4u;      // my x slot
    uint32_t r_eau, r_mb;
    asm("mapa.shared::cluster.u32 %0, %1, %2;" : "=r"(r_eau) : "r"(l_eau), "r"(rank ^ 1));
    asm("mapa.shared::cluster.u32 %0, %1, %2;" : "=r"(r_mb)  : "r"(l_mb),  "r"(rank ^ 1));

    // ---- forward recursion ----
    // iter t: reads buf pb=(t-1)&1, writes buf sb=t&1; wait on mb[pb] (peer's
    // x_{t-1} delivery; t=1 satisfied by prime). wpar0/wpar1 = next parity per mb.
    uint32_t wpar0 = 0u, wpar1 = 0u;
    for (int t = 1; t < L; t++) {
        const uint32_t sb   = (uint32_t)(t & 1);
        const uint32_t pboff = (sb ^ 1u) << 10;    // pb * 1024
        const uint32_t sboff = sb << 10;

        __syncthreads();                            // bar1: local STS(t-1)/prefill visible

        if (tid == 0)
            asm volatile("mbarrier.arrive.expect_tx.shared.b64 _, [%0], 512;"
                         :: "r"(l_mb + sb * 8u) : "memory");

        // off-path prefetch (independent of ea)
        float peN = __expf(potR);                  // pe for t+1
        int tn = t + 2; tn = (tn < TT) ? tn : (TT - 1);
        float potR2 = __ldg(&pot[(b * TT + tn) * UU + u]);

        // ---- FFMA half 1: locally produced v's ----
        unsigned long long acc0 = 0ull, acc1 = 0ull;
        {
            const uint32_t ba = a_loc + pboff;
            #pragma unroll
            for (int i = 0; i < 16; i++) {
                unsigned long long a0, a1;
                asm volatile("ld.shared.v2.u64 {%0, %1}, [%2];"
                             : "=l"(a0), "=l"(a1) : "r"(ba + 16u * i));
                asm("fma.rn.f32x2 %0, %1, %2, %0;" : "+l"(acc0) : "l"(a0), "l"(em[2*i]));
                asm("fma.rn.f32x2 %0, %1, %2, %0;" : "+l"(acc1) : "l"(a1), "l"(em[2*i+1]));
            }
        }

        // ---- wait for peer's x_{t-1} (overlapped with half 1) ----
        {
            const uint32_t wp = (sb ^ 1u) ? wpar1 : wpar0;
            uint32_t done = 0;
            while (!done) {
                asm volatile(
                    "{ .reg .pred p;\n\t"
                    "mbarrier.try_wait.parity.acquire.cluster.shared::cta.b64 p, [%1], %2, 0x989680;\n\t"
                    "selp.b32 %0, 1, 0, p; }"
                    : "=r"(done) : "r"(l_mb + (sb ^ 1u) * 8u), "r"(wp) : "memory");
            }
            if (sb ^ 1u) wpar1 ^= 1u; else wpar0 ^= 1u;
        }

        // scale bookkeeping from x_{t-1}[0] (now visible for both ranks)
        float z;
        asm("ld.shared.f32 %0, [%1];" : "=f"(z) : "r"(l_ea + pboff));
        float qn = rcp_approx(z);
        Lq += __logf(z);

        // ---- FFMA half 2: peer-produced v's ----
        unsigned long long acc2 = 0ull, acc3 = 0ull;
        {
            const uint32_t ba = a_per + pboff;
            #pragma unroll
            for (int i = 0; i < 16; i++) {
                unsigned long long a0, a1;
                asm volatile("ld.shared.v2.u64 {%0, %1}, [%2];"
                             : "=l"(a0), "=l"(a1) : "r"(ba + 16u * i));
                asm("fma.rn.f32x2 %0, %1, %2, %0;" : "+l"(acc2) : "l"(a0), "l"(em[32+2*i]));
                asm("fma.rn.f32x2 %0, %1, %2, %0;" : "+l"(acc3) : "l"(a1), "l"(em[33+2*i]));
            }
        }

        // combine 4 accs + pair shfl -> full sum over 256 v
        unsigned long long s01, s23, sA;
        asm("add.rn.f32x2 %0, %1, %2;" : "=l"(s01) : "l"(acc0), "l"(acc1));
        asm("add.rn.f32x2 %0, %1, %2;" : "=l"(s23) : "l"(acc2), "l"(acc3));
        asm("add.rn.f32x2 %0, %1, %2;" : "=l"(sA)  : "l"(s01),  "l"(s23));
        float plo, phi;
        asm("mov.b64 {%0, %1}, %2;" : "=f"(plo), "=f"(phi) : "l"(sA));
        float S = plo + phi;
        S += __shfl_xor_sync(0xffffffffu, S, 1);   // partner covers the other 128 v

        float x = S * pe * qn;                     // identical in both pair threads

        if (h == 0) {
            asm volatile("st.shared.f32 [%0], %1;"
                         :: "r"(l_eau + sboff), "f"(x) : "memory");
            asm volatile("st.async.shared::cluster.mbarrier::complete_tx::bytes.b32 [%0], %1, [%2];"
                         :: "r"(r_eau + sboff), "r"(__float_as_uint(x)),
                            "r"(r_mb + sb * 8u) : "memory");
        }

        pe = peN; potR = potR2;
    }

    // ---- drain last phase (peer's x_{L-1}) so finalize sees full ea ----
    if (L > 1) {
        const uint32_t fb = (uint32_t)((L - 1) & 1);
        const uint32_t wp = fb ? wpar1 : wpar0;
        uint32_t done = 0;
        while (!done) {
            asm volatile(
                "{ .reg .pred p;\n\t"
                "mbarrier.try_wait.parity.acquire.cluster.shared::cta.b64 p, [%1], %2, 0x989680;\n\t"
                "selp.b32 %0, 1, 0, p; }"
                : "=r"(done) : "r"(l_mb + fb * 8u), "r"(wp) : "memory");
        }
    }
    __syncthreads();                                // local half of ea[fb] visible

    asm volatile("barrier.cluster.arrive.aligned;" ::: "memory");
    asm volatile("barrier.cluster.wait.aligned;" ::: "memory");

    // ---- finalize (rank 0): logZ = Lq + log(sum_u x_{L-1}[u]) ----
    if (rank == 0) {
        float s = sm.ea[(L - 1) & 1][tid];
        #pragma unroll
        for (int o = 16; o; o >>= 1) s += __shfl_xor_sync(0xffffffffu, s, o);
        if (lane == 0) sm.red[wid] = s;
        __syncthreads();
        if (tid == 0) {
            float tot = (sm.red[0] + sm.red[1]) + (sm.red[2] + sm.red[3])
                      + (sm.red[4] + sm.red[5]) + (sm.red[6] + sm.red[7]);
            g_ll[b] = sm.sscore - (Lq + __logf(tot));
        }
    }
}

// ---------------------------------------------------------------------------
__global__ void k_final(float* __restrict__ out) {
    __shared__ float r[2];
    float v = g_ll[threadIdx.x];   // 64 threads
    #pragma unroll
    for (int o = 16; o; o >>= 1) v += __shfl_xor_sync(0xffffffffu, v, o);
    if ((threadIdx.x & 31) == 0) r[threadIdx.x >> 5] = v;
    __syncthreads();
    if (threadIdx.x == 0) out[0] = -(r[0] + r[1]) * (1.0f / (float)BB);
}

// ---------------------------------------------------------------------------
extern "C" void kernel_launch(void* const* d_in, const int* in_sizes, int n_in,
                              void* d_out, int out_size) {
    (void)in_sizes; (void)n_in; (void)out_size;
    const float* pot    = (const float*)d_in[0];
    const int*   tags   = (const int*)  d_in[1];
    const int*   seqlen = (const int*)  d_in[2];
    const float* trans  = (const float*)d_in[3];
    float* out = (float*)d_out;

    k_forward<<<BB * 2, UU>>>(pot, tags, seqlen, trans);   // 64 clusters of 2 CTAs
    k_final<<<1, BB>>>(out);
}

// round 16
// speedup vs baseline: 1.3379x; 1.3379x over previous
#include <cuda_runtime.h>
#include <stdint.h>

#define BB 64
#define TT 512
#define UU 256
#define VH 128          // v-columns per CTA (cluster of 2 CTAs per batch)
#define SENT 0xBF800000u  // -1.0f; received partials are always >= +0.0f

__device__ float g_ll[BB];

// ---------------------------------------------------------------------------
__device__ __forceinline__ uint32_t s2u(const void* p) {
    uint32_t r;
    asm("{ .reg .u64 t; cvta.to.shared.u64 t, %1; cvt.u32.u64 %0, t; }" : "=r"(r) : "l"(p));
    return r;
}
__device__ __forceinline__ unsigned long long pack2(float lo, float hi) {
    unsigned long long r;
    asm("mov.b64 %0, {%1, %2};" : "=l"(r) : "f"(lo), "f"(hi));
    return r;
}
__device__ __forceinline__ float rcp_approx(float v) {
    float r;
    asm("rcp.approx.f32 %0, %1;" : "=f"(r) : "f"(v));
    return r;
}

struct __align__(16) Smem {
    float ea[UU];          // x_{t-1} (scaled exp-space alpha), indexed by v
    float recv[2][UU];     // peer partials, remote-store landing zone (1KB stride)
    float c0;              // broadcast of pot[b,0,0]
    float red[8];
    float sscore;
};

// ---------------------------------------------------------------------------
// k_forward: one 2-CTA cluster per batch; CTA rank r owns v in [r*128,(r+1)*128).
// Thread = u. E[v][u] for my v-half in 64 packed-f32x2 registers (round-9
// structure, proven at 237.6us). Exchange = plain st.relaxed.cluster remote
// store + per-thread sentinel polling (no mbarrier: no wakeup latency, no
// parity, threads unblock the moment their own word lands).
// Exp-space recursion: x_t = (P+R) * peqn; scale Lq accumulated off-path.
// ---------------------------------------------------------------------------
__global__ __launch_bounds__(256, 1) __cluster_dims__(2, 1, 1)
void k_forward(const float* __restrict__ pot,     // [B,T,U]
               const int*   __restrict__ tags,    // [B,T]
               const int*   __restrict__ seqlen,  // [B]
               const float* __restrict__ trans)   // [U,U]
{
    __shared__ Smem sm;
    const int u    = threadIdx.x;
    const int rank = blockIdx.x & 1;
    const int b    = blockIdx.x >> 1;
    const int lane = u & 31;
    const int wid  = u >> 5;
    const int L    = seqlen[b];

    // ---- init: sentinel both ring slots (before any peer store can arrive) ----
    sm.recv[0][u] = -1.0f;
    sm.recv[1][u] = -1.0f;
    asm volatile("barrier.cluster.arrive.aligned;" ::: "memory");

    // ---- E[v][u] = exp(trans[v][u]) for my v-half -> 64 f32x2 registers ----
    unsigned long long em[VH / 2];
    {
        const float* tb = trans + rank * VH * UU + u;
        #pragma unroll
        for (int j = 0; j < VH / 2; j++) {
            float f0 = __expf(__ldg(tb + (2 * j) * UU));
            float f1 = __expf(__ldg(tb + (2 * j + 1) * UU));
            em[j] = pack2(f0, f1);
        }
    }
    asm volatile("barrier.cluster.wait.aligned;" ::: "memory");

    // ---- path score (rank 0 only) ----
    if (rank == 0) {
        float sc = 0.0f;
        for (int t = u; t < L; t += 256) {
            int tg = __ldg(&tags[b * TT + t]);
            sc += __ldg(&pot[(b * TT + t) * UU + tg]);
            if (t >= 1) {
                int tp = __ldg(&tags[b * TT + t - 1]);
                sc += __ldg(&trans[tp * UU + tg]);
            }
        }
        #pragma unroll
        for (int o = 16; o; o >>= 1) sc += __shfl_xor_sync(0xffffffffu, sc, o);
        if (lane == 0) sm.red[wid] = sc;
        __syncthreads();
        if (u == 0)
            sm.sscore = (sm.red[0] + sm.red[1]) + (sm.red[2] + sm.red[3])
                      + (sm.red[4] + sm.red[5]) + (sm.red[6] + sm.red[7]);
    }

    // ---- init: x_0 = exp(pot0 - C0), Lq = C0 ----
    float p0 = pot[b * TT * UU + u];
    if (u == 0) sm.c0 = p0;
    __syncthreads();
    const float C0 = sm.c0;
    float x  = __expf(p0 - C0);     // x_0[0] == 1
    float Lq = C0;

    // ---- pot pipeline (2-deep): pe for t, raw for t+1 ----
    float pe   = __expf(__ldg(&pot[(b * TT + 1) * UU + u]));   // pe for t=1
    float potR = __ldg(&pot[(b * TT + 2) * UU + u]);           // raw for t=2

    // hoisted addresses
    const uint32_t ea_base = s2u(&sm.ea[0]) + (uint32_t)(rank * VH) * 4u;
    const uint32_t ea0     = s2u(&sm.ea[0]);
    const uint32_t l_recvu = s2u(&sm.recv[0][0]) + (uint32_t)u * 4u;
    uint32_t r_recvu;
    asm("mapa.shared::cluster.u32 %0, %1, %2;" : "=r"(r_recvu)
        : "r"(l_recvu), "r"(rank ^ 1));

    // ---- forward recursion (exp space) ----
    // ring slot = t&1 (starts 1); sentinel reset after each consume closes WAR
    // (peer's t+2 write causally follows my t+1 send, which follows my t reset
    //  by >600 cyc of fabric latency vs <35 cyc local commit).
    uint32_t bufoff = 1024u;
    for (int t = 1; t < L; t++) {
        sm.ea[u] = x;
        __syncthreads();                                    // bar1: x published

        // off-path: scale from x_{t-1}[0]; pot pipeline advance
        float z;
        asm("ld.shared.f32 %0, [%1];" : "=f"(z) : "r"(ea0));
        float qn   = rcp_approx(z);
        Lq += __logf(z);
        float peqn = pe * qn;
        float peN  = __expf(potR);                          // pe for t+1
        int tn = t + 2; tn = (tn < TT) ? tn : (TT - 1);
        float potR2 = __ldg(&pot[(b * TT + tn) * UU + u]);  // raw for t+2

        // P_u = sum over my v-half of x[v] * E[v][u]  (f32x2 packed)
        unsigned long long acc0 = 0ull, acc1 = 0ull;
        #pragma unroll
        for (int i = 0; i < VH / 4; i++) {
            unsigned long long a0, a1;
            asm volatile("ld.shared.v2.u64 {%0, %1}, [%2];"
                         : "=l"(a0), "=l"(a1) : "r"(ea_base + 16u * i));
            asm("fma.rn.f32x2 %0, %1, %2, %0;" : "+l"(acc0) : "l"(a0), "l"(em[2 * i]));
            asm("fma.rn.f32x2 %0, %1, %2, %0;" : "+l"(acc1) : "l"(a1), "l"(em[2 * i + 1]));
        }
        unsigned long long accs;
        asm("add.rn.f32x2 %0, %1, %2;" : "=l"(accs) : "l"(acc0), "l"(acc1));
        float plo, phi;
        asm("mov.b64 {%0, %1}, %2;" : "=f"(plo), "=f"(phi) : "l"(accs));
        float P = plo + phi;

        // send my partial to peer recv[buf][u] (plain relaxed remote store)
        asm volatile("st.relaxed.cluster.shared::cluster.b32 [%0], %1;"
                     :: "r"(r_recvu + bufoff), "r"(__float_as_uint(P)) : "memory");

        // poll my own word until the peer's value lands, then reset sentinel
        uint32_t rb;
        do {
            asm volatile("ld.relaxed.cluster.shared::cta.b32 %0, [%1];"
                         : "=r"(rb) : "r"(l_recvu + bufoff) : "memory");
        } while (rb == SENT);
        asm volatile("st.shared.b32 [%0], %1;"
                     :: "r"(l_recvu + bufoff), "r"(SENT) : "memory");

        float R = __uint_as_float(rb);
        x = (P + R) * peqn;         // commutative sum: identical in both CTAs

        pe = peN; potR = potR2;
        bufoff ^= 1024u;
    }

    // peer must have consumed all my sends before exit
    asm volatile("barrier.cluster.arrive.aligned;" ::: "memory");
    asm volatile("barrier.cluster.wait.aligned;" ::: "memory");

    // ---- finalize: logZ = Lq + log(sum_u x[u]); ll = score - logZ (rank 0) ----
    if (rank == 0) {
        float s = x;
        #pragma unroll
        for (int o = 16; o; o >>= 1) s += __shfl_xor_sync(0xffffffffu, s, o);
        if (lane == 0) sm.red[wid] = s;
        __syncthreads();
        if (u == 0) {
            float tot = (sm.red[0] + sm.red[1]) + (sm.red[2] + sm.red[3])
                      + (sm.red[4] + sm.red[5]) + (sm.red[6] + sm.red[7]);
            g_ll[b] = sm.sscore - (Lq + __logf(tot));
        }
    }
}

// ---------------------------------------------------------------------------
__global__ void k_final(float* __restrict__ out) {
    __shared__ float r[2];
    float v = g_ll[threadIdx.x];   // 64 threads
    #pragma unroll
    for (int o = 16; o; o >>= 1) v += __shfl_xor_sync(0xffffffffu, v, o);
    if ((threadIdx.x & 31) == 0) r[threadIdx.x >> 5] = v;
    __syncthreads();
    if (threadIdx.x == 0) out[0] = -(r[0] + r[1]) * (1.0f / (float)BB);
}

// ---------------------------------------------------------------------------
extern "C" void kernel_launch(void* const* d_in, const int* in_sizes, int n_in,
                              void* d_out, int out_size) {
    (void)in_sizes; (void)n_in; (void)out_size;
    const float* pot    = (const float*)d_in[0];
    const int*   tags   = (const int*)  d_in[1];
    const int*   seqlen = (const int*)  d_in[2];
    const float* trans  = (const float*)d_in[3];
    float* out = (float*)d_out;

    k_forward<<<BB * 2, UU>>>(pot, tags, seqlen, trans);   // 64 clusters of 2 CTAs
    k_final<<<1, BB>>>(out);
}